// round 6
// baseline (speedup 1.0000x reference)
#include <cuda_runtime.h>
#include <cuda_bf16.h>
#include <stdint.h>

// Problem constants (fixed by the dataset).
#define N_NODES 65536
#define N_EDGES 1048576
#define D 64

// Scratch: __device__ globals (no allocation allowed in kernel_launch).
__device__ __align__(16) float g_h[N_NODES * D];   // h = x @ W (16 MB)
__device__ float g_dinv[N_NODES];                  // deg^{-1/2}
__device__ int   g_deg[N_NODES];                   // degree incl. self-loop
__device__ int   g_row_start[N_NODES + 1];         // CSR row offsets (by dst)
__device__ int   g_cursor[N_NODES];                // fill cursors for reorder
__device__ int   g_csr_src[N_EDGES];               // src node per CSR slot

// ---------------------------------------------------------------------------
// Kernel 1: init degrees to 1 (self-loop).
__global__ void k_deg_init() {
    int i = blockIdx.x * blockDim.x + threadIdx.x;
    if (i < N_NODES) g_deg[i] = 1;
}

// Kernel 2: count in-degree at targets. 4 edges per thread via int4.
__global__ void k_deg_count(const int* __restrict__ ei) {
    int t = blockIdx.x * blockDim.x + threadIdx.x;
    if (t < N_EDGES / 4) {
        int4 d = ((const int4*)(ei + N_EDGES))[t];
        atomicAdd(&g_deg[d.x], 1);
        atomicAdd(&g_deg[d.y], 1);
        atomicAdd(&g_deg[d.z], 1);
        atomicAdd(&g_deg[d.w], 1);
    }
}

// Kernel 3: dinv = rsqrt(deg). deg >= 1 always (self-loop).
__global__ void k_dinv() {
    int i = blockIdx.x * blockDim.x + threadIdx.x;
    if (i < N_NODES) g_dinv[i] = rsqrtf((float)g_deg[i]);
}

// ---------------------------------------------------------------------------
// Kernel 4: exclusive scan of in-degree (g_deg - 1) -> CSR row offsets.
// Single block, 1024 threads, 64 nodes per thread.
__global__ __launch_bounds__(1024) void k_scan() {
    __shared__ int chunk[1024];
    const int tid = threadIdx.x;
    const int base = tid * 64;

    int s = 0;
    #pragma unroll
    for (int i = 0; i < 64; i++) s += g_deg[base + i] - 1;
    chunk[tid] = s;
    __syncthreads();

    // Hillis-Steele inclusive scan over 1024 chunk totals.
    for (int off = 1; off < 1024; off <<= 1) {
        int u = (tid >= off) ? chunk[tid - off] : 0;
        __syncthreads();
        chunk[tid] += u;
        __syncthreads();
    }
    int run = chunk[tid] - s;  // exclusive base for this chunk

    for (int i = 0; i < 64; i++) {
        int n = base + i;
        g_row_start[n] = run;
        g_cursor[n] = run;
        run += g_deg[n] - 1;
    }
    if (tid == 1023) g_row_start[N_NODES] = run;  // == N_EDGES
}

// Kernel 5: reorder edges into CSR (binned by dst).
__global__ __launch_bounds__(256) void k_reorder(const int* __restrict__ ei) {
    int e = blockIdx.x * blockDim.x + threadIdx.x;
    if (e < N_EDGES) {
        int src = ei[e];
        int dst = ei[N_EDGES + e];
        int pos = atomicAdd(&g_cursor[dst], 1);
        g_csr_src[pos] = src;
    }
}

// ---------------------------------------------------------------------------
// Kernel 6: h = x @ W (pure GEMM now; out is produced by k_pull).
// 128-row tile per block, 256 threads, 8x4 micro-tile per thread.
__global__ __launch_bounds__(256) void k_gemm(const float* __restrict__ x,
                                              const float* __restrict__ W) {
    __shared__ __align__(16) float xs[64 * 128];  // transposed: xs[k*128 + row]
    __shared__ __align__(16) float ws[64 * 64];   // row-major: ws[k*64 + j]

    const int tid = threadIdx.x;
    const int rowBase = blockIdx.x * 128;

    {
        const float4* Wv = (const float4*)W;
        float4* wsv = (float4*)ws;
        #pragma unroll
        for (int q = 0; q < 4; q++) wsv[tid + q * 256] = Wv[tid + q * 256];
    }
    {
        int row = tid & 127;
        int kq  = tid >> 7;  // 0..1
        const float4* xrow = (const float4*)&x[(size_t)(rowBase + row) * D];
        #pragma unroll
        for (int q = 0; q < 8; q++) {
            int k0 = kq * 32 + q * 4;
            float4 v = xrow[k0 >> 2];
            xs[(k0 + 0) * 128 + row] = v.x;
            xs[(k0 + 1) * 128 + row] = v.y;
            xs[(k0 + 2) * 128 + row] = v.z;
            xs[(k0 + 3) * 128 + row] = v.w;
        }
    }
    __syncthreads();

    const int ty = tid >> 4;
    const int tx = tid & 15;

    float acc[8][4] = {};
    #pragma unroll 8
    for (int k = 0; k < 64; k++) {
        float4 a0 = *(const float4*)&xs[k * 128 + ty * 8];
        float4 a1 = *(const float4*)&xs[k * 128 + ty * 8 + 4];
        float4 w4 = *(const float4*)&ws[k * 64 + tx * 4];
        float av[8] = {a0.x, a0.y, a0.z, a0.w, a1.x, a1.y, a1.z, a1.w};
        #pragma unroll
        for (int i = 0; i < 8; i++) {
            acc[i][0] += av[i] * w4.x;
            acc[i][1] += av[i] * w4.y;
            acc[i][2] += av[i] * w4.z;
            acc[i][3] += av[i] * w4.w;
        }
    }

    #pragma unroll
    for (int i = 0; i < 8; i++) {
        int r = rowBase + ty * 8 + i;
        *(float4*)&g_h[(size_t)r * D + tx * 4] =
            make_float4(acc[i][0], acc[i][1], acc[i][2], acc[i][3]);
    }
}

// ---------------------------------------------------------------------------
// Kernel 7: pull aggregation. 16 lanes per node; each lane owns one float4 of
// the feature vector and accumulates over in-neighbors in registers:
//   out[i] = b + dinv_i * sum_s dinv_s * h[s]  + dinv_i^2 * h[i]
// One plain STG.128 per lane — zero atomics.
__global__ __launch_bounds__(256) void k_pull(const float* __restrict__ b,
                                              float* __restrict__ out) {
    int t = blockIdx.x * blockDim.x + threadIdx.x;
    int node = t >> 4;
    int j4   = (t & 15) * 4;

    int beg = g_row_start[node];
    int end = g_row_start[node + 1];

    float4 acc = make_float4(0.f, 0.f, 0.f, 0.f);
    int k = beg;
    // 2-way unrolled for MLP.
    for (; k + 2 <= end; k += 2) {
        int s0 = g_csr_src[k];
        int s1 = g_csr_src[k + 1];
        float d0 = g_dinv[s0];
        float d1 = g_dinv[s1];
        float4 h0 = *(const float4*)&g_h[(size_t)s0 * D + j4];
        float4 h1 = *(const float4*)&g_h[(size_t)s1 * D + j4];
        acc.x += d0 * h0.x + d1 * h1.x;
        acc.y += d0 * h0.y + d1 * h1.y;
        acc.z += d0 * h0.z + d1 * h1.z;
        acc.w += d0 * h0.w + d1 * h1.w;
    }
    if (k < end) {
        int s0 = g_csr_src[k];
        float d0 = g_dinv[s0];
        float4 h0 = *(const float4*)&g_h[(size_t)s0 * D + j4];
        acc.x += d0 * h0.x; acc.y += d0 * h0.y;
        acc.z += d0 * h0.z; acc.w += d0 * h0.w;
    }

    float di = g_dinv[node];
    float s2 = di * di;
    float4 hv = *(const float4*)&g_h[(size_t)node * D + j4];
    float4 bv = *(const float4*)&b[j4];
    float4 ov = make_float4(bv.x + di * acc.x + s2 * hv.x,
                            bv.y + di * acc.y + s2 * hv.y,
                            bv.z + di * acc.z + s2 * hv.z,
                            bv.w + di * acc.w + s2 * hv.w);
    *(float4*)&out[(size_t)node * D + j4] = ov;
}

// ---------------------------------------------------------------------------
extern "C" void kernel_launch(void* const* d_in, const int* in_sizes, int n_in,
                              void* d_out, int out_size) {
    const float* x  = (const float*)d_in[0];
    const int*   ei = (const int*)d_in[1];    // [2, E] int32
    const float* W  = (const float*)d_in[2];
    const float* b  = (const float*)d_in[3];
    float* out = (float*)d_out;

    (void)in_sizes; (void)n_in; (void)out_size;

    k_gemm<<<N_NODES / 128, 256>>>(x, W);          // independent of degree chain
    k_deg_init<<<(N_NODES + 255) / 256, 256>>>();
    k_deg_count<<<(N_EDGES / 4 + 255) / 256, 256>>>(ei);
    k_dinv<<<(N_NODES + 255) / 256, 256>>>();
    k_scan<<<1, 1024>>>();
    k_reorder<<<(N_EDGES + 255) / 256, 256>>>(ei);
    k_pull<<<(N_NODES * 16) / 256, 256>>>(b, out);
}

// round 7
// speedup vs baseline: 2.6849x; 2.6849x over previous
#include <cuda_runtime.h>
#include <cuda_bf16.h>
#include <stdint.h>

// Problem constants (fixed by the dataset).
#define N_NODES 65536
#define N_EDGES 1048576
#define D 64

// Scratch: __device__ globals (no allocation allowed in kernel_launch).
__device__ __align__(16) float g_h[N_NODES * D];  // h = x @ W (16 MB)
__device__ float g_dinv[N_NODES];                 // deg^{-1/2} (incl. self-loop)
__device__ int   g_deg[N_NODES];                  // in-degree WITHOUT self-loop

// ---------------------------------------------------------------------------
// Kernel 1: count in-degree at targets. 4 edges per thread via int4.
// g_deg is zeroed by cudaMemsetAsync before this kernel.
__global__ void k_deg_count(const int* __restrict__ ei) {
    int t = blockIdx.x * blockDim.x + threadIdx.x;
    if (t < N_EDGES / 4) {
        int4 d = ((const int4*)(ei + N_EDGES))[t];
        atomicAdd(&g_deg[d.x], 1);
        atomicAdd(&g_deg[d.y], 1);
        atomicAdd(&g_deg[d.z], 1);
        atomicAdd(&g_deg[d.w], 1);
    }
}

// ---------------------------------------------------------------------------
// Kernel 2: h = x @ W with fused epilogue:
//   dinv[r] = rsqrt(deg[r] + 1)          (self-loop folded into +1)
//   out[r]  = h[r] * dinv[r]^2 + b       (self-loop message + bias)
// 128-row tile per block, 256 threads, 8x4 micro-tile per thread.
__global__ __launch_bounds__(256) void k_gemm(const float* __restrict__ x,
                                              const float* __restrict__ W,
                                              const float* __restrict__ b,
                                              float* __restrict__ out) {
    __shared__ __align__(16) float xs[64 * 128];  // transposed: xs[k*128 + row]
    __shared__ __align__(16) float ws[64 * 64];   // row-major: ws[k*64 + j]

    const int tid = threadIdx.x;
    const int rowBase = blockIdx.x * 128;

    // Load W: 1024 float4, 4 per thread.
    {
        const float4* Wv = (const float4*)W;
        float4* wsv = (float4*)ws;
        #pragma unroll
        for (int q = 0; q < 4; q++) wsv[tid + q * 256] = Wv[tid + q * 256];
    }
    // Load x tile transposed: row = tid&127, k-half kq = tid>>7.
    {
        int row = tid & 127;
        int kq  = tid >> 7;  // 0..1
        const float4* xrow = (const float4*)&x[(size_t)(rowBase + row) * D];
        #pragma unroll
        for (int q = 0; q < 8; q++) {
            int k0 = kq * 32 + q * 4;
            float4 v = xrow[k0 >> 2];
            xs[(k0 + 0) * 128 + row] = v.x;
            xs[(k0 + 1) * 128 + row] = v.y;
            xs[(k0 + 2) * 128 + row] = v.z;
            xs[(k0 + 3) * 128 + row] = v.w;
        }
    }
    __syncthreads();

    const int ty = tid >> 4;   // 0..15 -> rows ty*8 .. ty*8+7
    const int tx = tid & 15;   // 0..15 -> cols tx*4 .. tx*4+3

    float acc[8][4] = {};
    #pragma unroll 8
    for (int k = 0; k < 64; k++) {
        float4 a0 = *(const float4*)&xs[k * 128 + ty * 8];
        float4 a1 = *(const float4*)&xs[k * 128 + ty * 8 + 4];
        float4 w4 = *(const float4*)&ws[k * 64 + tx * 4];
        float av[8] = {a0.x, a0.y, a0.z, a0.w, a1.x, a1.y, a1.z, a1.w};
        #pragma unroll
        for (int i = 0; i < 8; i++) {
            acc[i][0] += av[i] * w4.x;
            acc[i][1] += av[i] * w4.y;
            acc[i][2] += av[i] * w4.z;
            acc[i][3] += av[i] * w4.w;
        }
    }

    // Epilogue: dinv, h, and out = h*dinv^2 + b.
    float4 bv = *(const float4*)&b[tx * 4];
    #pragma unroll
    for (int i = 0; i < 8; i++) {
        int r = rowBase + ty * 8 + i;
        float di = rsqrtf((float)(g_deg[r] + 1));
        g_dinv[r] = di;                 // 16 lanes write same value: benign
        float s = di * di;
        float4 hv = make_float4(acc[i][0], acc[i][1], acc[i][2], acc[i][3]);
        *(float4*)&g_h[(size_t)r * D + tx * 4] = hv;
        float4 ov = make_float4(hv.x * s + bv.x, hv.y * s + bv.y,
                                hv.z * s + bv.z, hv.w * s + bv.w);
        *(float4*)&out[(size_t)r * D + tx * 4] = ov;
    }
}

// ---------------------------------------------------------------------------
// Kernel 3: edge scatter (UNCHANGED hot loop — at the LTS byte floor).
// 16 lanes per edge; each lane: one float4 gather + one red.global.add.v4.f32.
__global__ __launch_bounds__(256) void k_scatter(const int* __restrict__ ei,
                                                 float* __restrict__ out) {
    long long t = (long long)blockIdx.x * blockDim.x + threadIdx.x;
    int e  = (int)(t >> 4);
    int j4 = ((int)t & 15) * 4;
    if (e >= N_EDGES) return;

    int src = ei[e];
    int dst = ei[N_EDGES + e];
    float norm = g_dinv[src] * g_dinv[dst];

    float4 hv = *(const float4*)&g_h[(size_t)src * D + j4];
    float4 m = make_float4(hv.x * norm, hv.y * norm, hv.z * norm, hv.w * norm);

    float* p = &out[(size_t)dst * D + j4];
    asm volatile("red.global.add.v4.f32 [%0], {%1, %2, %3, %4};"
                 :: "l"(p), "f"(m.x), "f"(m.y), "f"(m.z), "f"(m.w)
                 : "memory");
}

// ---------------------------------------------------------------------------
extern "C" void kernel_launch(void* const* d_in, const int* in_sizes, int n_in,
                              void* d_out, int out_size) {
    const float* x  = (const float*)d_in[0];
    const int*   ei = (const int*)d_in[1];    // [2, E] int32
    const float* W  = (const float*)d_in[2];
    const float* b  = (const float*)d_in[3];
    float* out = (float*)d_out;

    (void)in_sizes; (void)n_in; (void)out_size;

    void* deg_ptr = nullptr;
    cudaGetSymbolAddress(&deg_ptr, g_deg);
    cudaMemsetAsync(deg_ptr, 0, N_NODES * sizeof(int));

    k_deg_count<<<(N_EDGES / 4 + 255) / 256, 256>>>(ei);
    k_gemm<<<N_NODES / 128, 256>>>(x, W, b, out);

    long long scatter_threads = (long long)N_EDGES * 16;
    k_scatter<<<(unsigned)((scatter_threads + 255) / 256), 256>>>(ei, out);
}

// round 8
// speedup vs baseline: 2.9415x; 1.0956x over previous
#include <cuda_runtime.h>
#include <cuda_bf16.h>
#include <stdint.h>

// Problem constants (fixed by the dataset).
#define N_NODES 65536
#define N_EDGES 1048576
#define D 64

#define GEMM_BLOCKS (N_NODES / 128)            // 512
#define DEG_BLOCKS  (N_EDGES / 4 / 256)        // 1024

// Scratch: __device__ globals (no allocation allowed in kernel_launch).
__device__ __align__(16) float g_h[N_NODES * D];  // h = x @ W (16 MB)
__device__ float g_dinv[N_NODES];                 // deg^{-1/2} (incl. self-loop)
__device__ int   g_deg[N_NODES];                  // in-degree WITHOUT self-loop

// ---------------------------------------------------------------------------
// Fused kernel: blocks [0,512) run the GEMM mainloop (h = x @ W -> g_h);
// blocks [512,1536) run the degree count. The two phases use disjoint HW
// (FMA/smem vs L2 atomics), so the deg count hides under the GEMM.
__global__ __launch_bounds__(256) void k_fused(const float* __restrict__ x,
                                               const float* __restrict__ W,
                                               const int* __restrict__ ei) {
    __shared__ __align__(16) float xs[64 * 128];  // transposed: xs[k*128 + row]
    __shared__ __align__(16) float ws[64 * 64];   // row-major: ws[k*64 + j]

    const int tid = threadIdx.x;

    if (blockIdx.x >= GEMM_BLOCKS) {
        // ---- degree-count phase: 4 edges per thread via int4 ----
        int t = (blockIdx.x - GEMM_BLOCKS) * 256 + tid;
        int4 d = ((const int4*)(ei + N_EDGES))[t];
        atomicAdd(&g_deg[d.x], 1);
        atomicAdd(&g_deg[d.y], 1);
        atomicAdd(&g_deg[d.z], 1);
        atomicAdd(&g_deg[d.w], 1);
        return;
    }

    // ---- GEMM phase: 128-row tile, 8x4 micro-tile per thread ----
    const int rowBase = blockIdx.x * 128;

    {
        const float4* Wv = (const float4*)W;
        float4* wsv = (float4*)ws;
        #pragma unroll
        for (int q = 0; q < 4; q++) wsv[tid + q * 256] = Wv[tid + q * 256];
    }
    {
        int row = tid & 127;
        int kq  = tid >> 7;  // 0..1
        const float4* xrow = (const float4*)&x[(size_t)(rowBase + row) * D];
        #pragma unroll
        for (int q = 0; q < 8; q++) {
            int k0 = kq * 32 + q * 4;
            float4 v = xrow[k0 >> 2];
            xs[(k0 + 0) * 128 + row] = v.x;
            xs[(k0 + 1) * 128 + row] = v.y;
            xs[(k0 + 2) * 128 + row] = v.z;
            xs[(k0 + 3) * 128 + row] = v.w;
        }
    }
    __syncthreads();

    const int ty = tid >> 4;   // 0..15 -> rows ty*8 .. ty*8+7
    const int tx = tid & 15;   // 0..15 -> cols tx*4 .. tx*4+3

    float acc[8][4] = {};
    #pragma unroll 8
    for (int k = 0; k < 64; k++) {
        float4 a0 = *(const float4*)&xs[k * 128 + ty * 8];
        float4 a1 = *(const float4*)&xs[k * 128 + ty * 8 + 4];
        float4 w4 = *(const float4*)&ws[k * 64 + tx * 4];
        float av[8] = {a0.x, a0.y, a0.z, a0.w, a1.x, a1.y, a1.z, a1.w};
        #pragma unroll
        for (int i = 0; i < 8; i++) {
            acc[i][0] += av[i] * w4.x;
            acc[i][1] += av[i] * w4.y;
            acc[i][2] += av[i] * w4.z;
            acc[i][3] += av[i] * w4.w;
        }
    }

    #pragma unroll
    for (int i = 0; i < 8; i++) {
        int r = rowBase + ty * 8 + i;
        *(float4*)&g_h[(size_t)r * D + tx * 4] =
            make_float4(acc[i][0], acc[i][1], acc[i][2], acc[i][3]);
    }
}

// ---------------------------------------------------------------------------
// Finish kernel: dinv = rsqrt(deg+1); out = h*dinv^2 + b (self-loop + bias).
// 16 lanes per node, one float4 each. Streaming, ~33MB total.
__global__ __launch_bounds__(256) void k_finish(const float* __restrict__ b,
                                                float* __restrict__ out) {
    int t = blockIdx.x * blockDim.x + threadIdx.x;
    int node = t >> 4;
    int j4   = (t & 15) * 4;

    float di = rsqrtf((float)(g_deg[node] + 1));
    if ((t & 15) == 0) g_dinv[node] = di;
    float s = di * di;

    float4 hv = *(const float4*)&g_h[(size_t)node * D + j4];
    float4 bv = *(const float4*)&b[j4];
    *(float4*)&out[(size_t)node * D + j4] =
        make_float4(hv.x * s + bv.x, hv.y * s + bv.y,
                    hv.z * s + bv.z, hv.w * s + bv.w);
}

// ---------------------------------------------------------------------------
// Edge scatter (UNCHANGED hot loop — at the LTS byte floor).
// 16 lanes per edge; each lane: one float4 gather + one red.global.add.v4.f32.
__global__ __launch_bounds__(256) void k_scatter(const int* __restrict__ ei,
                                                 float* __restrict__ out) {
    long long t = (long long)blockIdx.x * blockDim.x + threadIdx.x;
    int e  = (int)(t >> 4);
    int j4 = ((int)t & 15) * 4;
    if (e >= N_EDGES) return;

    int src = ei[e];
    int dst = ei[N_EDGES + e];
    float norm = g_dinv[src] * g_dinv[dst];

    float4 hv = *(const float4*)&g_h[(size_t)src * D + j4];
    float4 m = make_float4(hv.x * norm, hv.y * norm, hv.z * norm, hv.w * norm);

    float* p = &out[(size_t)dst * D + j4];
    asm volatile("red.global.add.v4.f32 [%0], {%1, %2, %3, %4};"
                 :: "l"(p), "f"(m.x), "f"(m.y), "f"(m.z), "f"(m.w)
                 : "memory");
}

// ---------------------------------------------------------------------------
extern "C" void kernel_launch(void* const* d_in, const int* in_sizes, int n_in,
                              void* d_out, int out_size) {
    const float* x  = (const float*)d_in[0];
    const int*   ei = (const int*)d_in[1];    // [2, E] int32
    const float* W  = (const float*)d_in[2];
    const float* b  = (const float*)d_in[3];
    float* out = (float*)d_out;

    (void)in_sizes; (void)n_in; (void)out_size;

    void* deg_ptr = nullptr;
    cudaGetSymbolAddress(&deg_ptr, g_deg);
    cudaMemsetAsync(deg_ptr, 0, N_NODES * sizeof(int));

    k_fused<<<GEMM_BLOCKS + DEG_BLOCKS, 256>>>(x, W, ei);
    k_finish<<<(N_NODES * 16) / 256, 256>>>(b, out);

    long long scatter_threads = (long long)N_EDGES * 16;
    k_scatter<<<(unsigned)((scatter_threads + 255) / 256), 256>>>(ei, out);
}